// round 8
// baseline (speedup 1.0000x reference)
#include <cuda_runtime.h>
#include <math.h>

#define BB 32
#define NN 512
#define NH 8
#define NWRD 16   // 512/32 bitmask words per adjacency row

typedef unsigned long long u64t;

// packed f32x2 helpers (FFMA2 is PTX-only: fma.rn.f32x2)
__device__ __forceinline__ u64t ffma2(u64t a, u64t b, u64t c) {
  u64t d; asm("fma.rn.f32x2 %0, %1, %2, %3;" : "=l"(d) : "l"(a), "l"(b), "l"(c));
  return d;
}
__device__ __forceinline__ u64t bcast2(float x) {
  u64t d; asm("mov.b64 %0, {%1, %1};" : "=l"(d) : "f"(x));
  return d;
}
__device__ __forceinline__ float2 unpk(u64t d) {
  float2 r; asm("mov.b64 {%0, %1}, %2;" : "=f"(r.x), "=f"(r.y) : "l"(d));
  return r;
}

// ---------------- scratch (device globals; no allocations) ----------------
__device__ unsigned g_bits[BB*NN*NWRD];          // adjacency bitmask
__device__ float g_Wh1[BB*NN*512];               // layer1 per-head projections (concat)
__device__ float g_x1 [BB*NN*512];               // layer1 output (ELU'd concat)
__device__ float g_Wh2[BB*NN*128];               // layer2 projection
__device__ float g_att2[BB*NN*128];              // layer2 GAT output
// per-(node,head) layer1 score factors: A=exp(s1), C=exp(.2 s1), P=exp(s2), Q=exp(.2 s2)
__device__ float g_s1a[BB*NN*NH], g_s2a[BB*NN*NH];
__device__ float g_Aa [BB*NN*NH], g_Ca [BB*NN*NH];
__device__ float g_Pa [BB*NN*NH], g_Qa [BB*NN*NH];
// per-node layer2 score factors
__device__ float g_s1b[BB*NN], g_s2b[BB*NN];
__device__ float g_Ab [BB*NN], g_Cb [BB*NN];
__device__ float g_Pb [BB*NN], g_Qb [BB*NN];

// ---------------- adjacency bitmask ----------------
__global__ void k_bits(const int* __restrict__ adj) {
  int row = blockIdx.x;                      // b*NN + i
  const int* a = adj + (size_t)row*NN;
  int lane = threadIdx.x & 31, w = threadIdx.x >> 5;
  for (int c = w; c < NWRD; c += 2) {
    unsigned m = __ballot_sync(0xffffffffu, a[c*32 + lane] > 0);
    if (lane == 0) g_bits[row*NWRD + c] = m;
  }
}

// ---------------- projection SGEMM: 128x64 tile, 8x8 microtile, 128 threads ----------------
// MODE 1: A=graph_inf (K=128), B=W_heads [h][f][o] -> col h*64+o, C=g_Wh1 (ldc 512)
// MODE 2: A=g_x1 (K=512),      B=W_out [512,128],                 C=g_Wh2 (ldc 128)
template<int K, int MODE>
__global__ __launch_bounds__(128, 4) void k_proj(const float* __restrict__ Ain,
                                                 const float* __restrict__ Bsrc) {
  __shared__ float As[16][132];
  __shared__ float Bs[16][68];
  const float* A = (MODE==1) ? Ain : g_x1;
  float* C = (MODE==1) ? g_Wh1 : g_Wh2;
  const int ldc = (MODE==1) ? 512 : 128;
  int m0 = blockIdx.x*128, n0 = blockIdx.y*64;
  int tid = threadIdx.x;
  int tx = tid & 7, ty = tid >> 3;        // tx: 8 f-groups of 8, ty: 16 i-groups of 8
  u64t acc2[4][8];
#pragma unroll
  for (int i=0;i<4;i++)
#pragma unroll
    for (int j=0;j<8;j++) acc2[i][j] = 0ull;
  for (int k0 = 0; k0 < K; k0 += 16) {
    // A tile: 128 rows x 16 k (transposed into As[k][m]); 512 float4, 4/thread
#pragma unroll
    for (int r = 0; r < 4; r++) {
      int m = (tid >> 2) + r*32, kq = (tid & 3) * 4;
      float4 v = *(const float4*)(A + (size_t)(m0+m)*K + k0 + kq);
      As[kq+0][m]=v.x; As[kq+1][m]=v.y; As[kq+2][m]=v.z; As[kq+3][m]=v.w;
    }
    // B tile: 16 k x 64 n; 256 float4, 2/thread
#pragma unroll
    for (int r = 0; r < 2; r++) {
      int task = tid + r*128;
      int k = task >> 4, n4 = (task & 15) * 4;
      float4 v;
      if (MODE==1) {
        int h = n0 >> 6;   // N-tile == head width
        v = *(const float4*)(Bsrc + ((size_t)h*128 + k0 + k)*64 + n4);
      } else {
        v = *(const float4*)(Bsrc + (size_t)(k0+k)*128 + n0 + n4);
      }
      *(float4*)&Bs[k][n4] = v;
    }
    __syncthreads();
#pragma unroll 4
    for (int kk = 0; kk < 16; kk++) {
      ulonglong2 q0 = *(const ulonglong2*)&As[kk][ty*8];
      ulonglong2 q1 = *(const ulonglong2*)&As[kk][ty*8+4];
      float4 b0 = *(const float4*)&Bs[kk][tx*8];
      float4 b1 = *(const float4*)&Bs[kk][tx*8+4];
      u64t bb[8] = {bcast2(b0.x),bcast2(b0.y),bcast2(b0.z),bcast2(b0.w),
                    bcast2(b1.x),bcast2(b1.y),bcast2(b1.z),bcast2(b1.w)};
      u64t aa[4] = {q0.x,q0.y,q1.x,q1.y};
#pragma unroll
      for (int ip=0;ip<4;ip++)
#pragma unroll
        for (int f=0;f<8;f++) acc2[ip][f] = ffma2(aa[ip], bb[f], acc2[ip][f]);
    }
    __syncthreads();
  }
#pragma unroll
  for (int ip=0;ip<4;ip++) {
    float2 u[8];
#pragma unroll
    for (int f=0;f<8;f++) u[f] = unpk(acc2[ip][f]);
    int ii0 = ty*8 + 2*ip;
    *(float4*)(C + (size_t)(m0 + ii0)*ldc + n0 + tx*8)     = make_float4(u[0].x,u[1].x,u[2].x,u[3].x);
    *(float4*)(C + (size_t)(m0 + ii0)*ldc + n0 + tx*8 + 4) = make_float4(u[4].x,u[5].x,u[6].x,u[7].x);
    *(float4*)(C + (size_t)(m0 + ii0+1)*ldc + n0 + tx*8)     = make_float4(u[0].y,u[1].y,u[2].y,u[3].y);
    *(float4*)(C + (size_t)(m0 + ii0+1)*ldc + n0 + tx*8 + 4) = make_float4(u[4].y,u[5].y,u[6].y,u[7].y);
  }
}

// ---------------- layer1 scores: s1,s2 per (node,head) + A,C,P,Q ----------------
__global__ __launch_bounds__(256) void k_scores1(const float* __restrict__ a_heads) {
  int row = blockIdx.x;                    // b*NN + n
  int w = threadIdx.x >> 5, l = threadIdx.x & 31;   // warp = head
  const float* wh = g_Wh1 + (size_t)row*512 + w*64;
  const float* ah = a_heads + w*128;
  float s1 = wh[l]*ah[l]    + wh[l+32]*ah[l+32];
  float s2 = wh[l]*ah[64+l] + wh[l+32]*ah[96+l];
  for (int d=16; d; d>>=1) {
    s1 += __shfl_xor_sync(0xffffffffu, s1, d);
    s2 += __shfl_xor_sync(0xffffffffu, s2, d);
  }
  if (l == 0) {
    int idx = row*NH + w;
    g_s1a[idx] = s1; g_s2a[idx] = s2;
    g_Aa[idx] = __expf(s1); g_Ca[idx] = __expf(0.2f*s1);
    g_Pa[idx] = __expf(s2); g_Qa[idx] = __expf(0.2f*s2);
  }
}

// ---------------- layer2 scores ----------------
__global__ __launch_bounds__(256) void k_scores2(const float* __restrict__ a_out) {
  int row = blockIdx.x*8 + (threadIdx.x >> 5);
  int l = threadIdx.x & 31;
  const float* wh = g_Wh2 + (size_t)row*128;
  float s1=0.f, s2=0.f;
#pragma unroll
  for (int r=0;r<4;r++){
    int o=l+r*32; float x=wh[o];
    s1 = fmaf(x, a_out[o], s1);
    s2 = fmaf(x, a_out[128+o], s2);
  }
  for (int d=16; d; d>>=1) {
    s1 += __shfl_xor_sync(0xffffffffu, s1, d);
    s2 += __shfl_xor_sync(0xffffffffu, s2, d);
  }
  if (l==0) {
    g_s1b[row]=s1; g_s2b[row]=s2;
    g_Ab[row]=__expf(s1); g_Cb[row]=__expf(0.2f*s1);
    g_Pb[row]=__expf(s2); g_Qb[row]=__expf(0.2f*s2);
  }
}

// ---------------- fused masked-softmax attention @ Wh ----------------
// 128x64 output tile, 8x8 microtile, 128 threads, j-tile = 32.
// p-gen thread owns full row i=tid -> pure register rowsum.
template<int LAYER>
__global__ __launch_bounds__(128, 4) void k_att(const float* __restrict__ masks) {
  __shared__ float pT[32][132];    // [j][i]
  __shared__ float WhS[32][68];    // [j][f]
  __shared__ float s2j[32], Pj[32], Qj[32];
  __shared__ float rsinv[128];
  int b = blockIdx.z, sec = blockIdx.y, it = blockIdx.x;
  int i0 = it*128;
  int tid = threadIdx.x;
  int tx = tid & 7, ty = tid >> 3;
  const float* Wh = (LAYER==1) ? g_Wh1 : g_Wh2;
  const int ldw   = (LAYER==1) ? 512 : 128;
  const int coff  = sec*64;
  // per-thread row-i factors (thread owns i = tid)
  float ms1, mA, mC;
  {
    int node = b*NN + i0 + tid;
    int si = (LAYER==1) ? node*NH + sec : node;
    ms1 = (LAYER==1) ? g_s1a[si] : g_s1b[si];
    mA  = (LAYER==1) ? g_Aa[si]  : g_Ab[si];
    mC  = (LAYER==1) ? g_Ca[si]  : g_Cb[si];
  }
  const unsigned* bitrow = g_bits + (size_t)(b*NN + i0 + tid)*NWRD;
  u64t acc2[4][8];
#pragma unroll
  for (int i=0;i<4;i++)
#pragma unroll
    for (int j=0;j<8;j++) acc2[i][j] = 0ull;
  float rsacc = 0.f;
  for (int jt = 0; jt < 16; jt++) {
    __syncthreads();
    // Wh tile: 32 rows x 64 cols = 512 float4, 4/thread
#pragma unroll
    for (int r = 0; r < 4; r++) {
      int task = tid + r*128;
      int j = task >> 4, c4 = (task & 15) * 4;
      float4 v = *(const float4*)(Wh + (size_t)(b*NN + jt*32 + j)*ldw + coff + c4);
      *(float4*)&WhS[j][c4] = v;
    }
    if (tid < 32) {
      int node = b*NN + jt*32 + tid;
      int si = (LAYER==1) ? node*NH + sec : node;
      s2j[tid] = (LAYER==1) ? g_s2a[si] : g_s2b[si];
      Pj[tid]  = (LAYER==1) ? g_Pa[si]  : g_Pb[si];
      Qj[tid]  = (LAYER==1) ? g_Qa[si]  : g_Qb[si];
    }
    __syncthreads();
    // p-gen: thread fills column i=tid of the 32-j tile
    {
      unsigned wrd = bitrow[jt];
#pragma unroll 8
      for (int j = 0; j < 32; j++) {
        float p = 0.f;
        if ((wrd >> j) & 1u) {
          float sv = ms1 + s2j[j];
          p = (sv > 0.f) ? mA*Pj[j] : mC*Qj[j];
        }
        pT[j][tid] = p;
        rsacc += p;
      }
    }
    __syncthreads();
#pragma unroll 4
    for (int jj = 0; jj < 32; jj++) {
      ulonglong2 q0 = *(const ulonglong2*)&pT[jj][ty*8];
      ulonglong2 q1 = *(const ulonglong2*)&pT[jj][ty*8+4];
      float4 b0 = *(const float4*)&WhS[jj][tx*8];
      float4 b1 = *(const float4*)&WhS[jj][tx*8+4];
      u64t bb[8] = {bcast2(b0.x),bcast2(b0.y),bcast2(b0.z),bcast2(b0.w),
                    bcast2(b1.x),bcast2(b1.y),bcast2(b1.z),bcast2(b1.w)};
      u64t aa[4] = {q0.x,q0.y,q1.x,q1.y};
#pragma unroll
      for (int ip=0;ip<4;ip++)
#pragma unroll
        for (int f=0;f<8;f++) acc2[ip][f] = ffma2(aa[ip], bb[f], acc2[ip][f]);
    }
  }
  __syncthreads();
  rsinv[tid] = (rsacc > 0.f) ? 1.f/rsacc : 0.f;
  __syncthreads();
  float* outp = (LAYER==1) ? g_x1 : g_att2;
  const int ldo = (LAYER==1) ? 512 : 128;
#pragma unroll
  for (int ip = 0; ip < 4; ip++) {
    float2 u[8];
#pragma unroll
    for (int f=0;f<8;f++) u[f] = unpk(acc2[ip][f]);
#pragma unroll
    for (int half = 0; half < 2; half++) {
      int ii = ty*8 + 2*ip + half;
      float mk = masks[b*NN + i0 + ii];
      float scale = rsinv[ii] * ((LAYER==1) ? mk : mk*mk);
      float v[8];
#pragma unroll
      for (int f=0;f<8;f++) {
        float x = (half ? u[f].y : u[f].x) * scale;
        if (LAYER==1) x = (x > 0.f) ? x : expm1f(x);   // ELU
        v[f] = x;
      }
      *(float4*)(outp + (size_t)(b*NN + i0 + ii)*ldo + coff + tx*8) =
          make_float4(v[0],v[1],v[2],v[3]);
      *(float4*)(outp + (size_t)(b*NN + i0 + ii)*ldo + coff + tx*8 + 4) =
          make_float4(v[4],v[5],v[6],v[7]);
    }
  }
}

// ---------------- node select + 3-layer MLP + softmax ----------------
// node_order dtype sniff: reference declares int64 but JAX default (x64 off)
// yields int32. If int64, odd int32 slots of the first 32 are all 0.
__global__ __launch_bounds__(256) void k_mlp(
    const int* __restrict__ node_order_i32,
    const float* __restrict__ work, const float* __restrict__ sub,
    const float* __restrict__ w1, const float* __restrict__ b1,
    const float* __restrict__ w2, const float* __restrict__ b2,
    const float* __restrict__ w3, const float* __restrict__ b3,
    float* __restrict__ out) {
  __shared__ float inf[192];
  __shared__ float h1[256];
  __shared__ float h2[256];
  __shared__ float red[8];
  __shared__ float sval;
  __shared__ int snd;
  int b = blockIdx.x, t = threadIdx.x;
  if (t == 0) {
    bool is64 = true;
    for (int i = 1; i < 32; i += 2) is64 = is64 && (node_order_i32[i] == 0);
    snd = is64 ? node_order_i32[2*b] : node_order_i32[b];
  }
  __syncthreads();
  int nd = snd;
  const float* sel = g_att2 + ((size_t)b*NN + nd)*128;
  if (t < 128)       inf[t] = sel[t];
  else if (t < 160)  inf[t] = work[b*32 + (t-128)];
  else if (t < 192)  inf[t] = sub[b*32 + (t-160)];
  __syncthreads();
  float s = b1[t];
  for (int k=0;k<192;k++) s = fmaf(inf[k], w1[k*256+t], s);
  h1[t] = fmaxf(s, 0.f);
  __syncthreads();
  s = b2[t];
  for (int k=0;k<256;k++) s = fmaf(h1[k], w2[k*256+t], s);
  h2[t] = fmaxf(s, 0.f);
  __syncthreads();
  float s0 = b3[t], s1 = b3[256+t];
  for (int k=0;k<256;k++) {
    float h = h2[k];
    s0 = fmaf(h, w3[k*512+t], s0);
    s1 = fmaf(h, w3[k*512+256+t], s1);
  }
  float mx = fmaxf(s0, s1);
  for (int d=16; d; d>>=1) mx = fmaxf(mx, __shfl_xor_sync(0xffffffffu, mx, d));
  if ((t&31)==0) red[t>>5] = mx;
  __syncthreads();
  if (t == 0) { float m = red[0]; for (int i=1;i<8;i++) m = fmaxf(m, red[i]); sval = m; }
  __syncthreads();
  float m = sval;
  float e0 = __expf(s0 - m), e1 = __expf(s1 - m);
  float ps = e0 + e1;
  for (int d=16; d; d>>=1) ps += __shfl_xor_sync(0xffffffffu, ps, d);
  if ((t&31)==0) red[t>>5] = ps;
  __syncthreads();
  if (t == 0) { float q = 0.f; for (int i=0;i<8;i++) q += red[i]; sval = q; }
  __syncthreads();
  float inv = 1.f / sval;
  out[b*512 + t]       = e0*inv;
  out[b*512 + 256 + t] = e1*inv;
}

// ---------------- launcher ----------------
extern "C" void kernel_launch(void* const* d_in, const int* in_sizes, int n_in,
                              void* d_out, int out_size) {
  const float* graph_inf  = (const float*)d_in[0];
  const int*   adj        = (const int*)d_in[1];
  const float* masks      = (const float*)d_in[2];
  const int*   node_order = (const int*)d_in[3];
  const float* work       = (const float*)d_in[4];
  const float* subtask    = (const float*)d_in[5];
  const float* W_heads    = (const float*)d_in[6];
  const float* a_heads    = (const float*)d_in[7];
  const float* W_out      = (const float*)d_in[8];
  const float* a_out      = (const float*)d_in[9];
  const float* fc1w       = (const float*)d_in[10];
  const float* fc1b       = (const float*)d_in[11];
  const float* fc2w       = (const float*)d_in[12];
  const float* fc2b       = (const float*)d_in[13];
  const float* fc3w       = (const float*)d_in[14];
  const float* fc3b       = (const float*)d_in[15];
  float* out = (float*)d_out;
  (void)in_sizes; (void)n_in; (void)out_size;

  k_bits<<<BB*NN, 64>>>(adj);
  k_proj<128,1><<<dim3(128, 8), 128>>>(graph_inf, W_heads);
  k_scores1<<<BB*NN, 256>>>(a_heads);
  k_att<1><<<dim3(4, 8, BB), 128>>>(masks);
  k_proj<512,2><<<dim3(128, 2), 128>>>(nullptr, W_out);
  k_scores2<<<BB*NN/8, 256>>>(a_out);
  k_att<2><<<dim3(4, 2, BB), 128>>>(masks);
  k_mlp<<<BB, 256>>>(node_order, work, subtask,
                     fc1w, fc1b, fc2w, fc2b, fc3w, fc3b, out);
}

// round 10
// speedup vs baseline: 1.5883x; 1.5883x over previous
#include <cuda_runtime.h>
#include <math.h>
#include <stdint.h>

#define BB 32
#define NN 512
#define NH 8
#define NWRD 16   // 512/32 bitmask words per adjacency row

typedef unsigned long long u64t;

// ---------------- ptx helpers ----------------
__device__ __forceinline__ u64t ffma2(u64t a, u64t b, u64t c) {
  u64t d; asm("fma.rn.f32x2 %0, %1, %2, %3;" : "=l"(d) : "l"(a), "l"(b), "l"(c));
  return d;
}
__device__ __forceinline__ u64t bcast2(float x) {
  u64t d; asm("mov.b64 %0, {%1, %1};" : "=l"(d) : "f"(x));
  return d;
}
__device__ __forceinline__ float2 unpk(u64t d) {
  float2 r; asm("mov.b64 {%0, %1}, %2;" : "=f"(r.x), "=f"(r.y) : "l"(d));
  return r;
}
__device__ __forceinline__ float tf32r(float x) {
  float r; asm("cvt.rna.tf32.f32 %0, %1;" : "=f"(r) : "f"(x));
  return r;
}
// warp-level tf32 MMA (Ampere-style; runs via HMMA fallback on sm_103)
__device__ __forceinline__ void mma_tf32(float* d, uint32_t a0, uint32_t a1,
                                         uint32_t a2, uint32_t a3,
                                         uint32_t b0, uint32_t b1) {
  asm volatile(
      "mma.sync.aligned.m16n8k8.row.col.f32.tf32.tf32.f32 "
      "{%0,%1,%2,%3}, {%4,%5,%6,%7}, {%8,%9}, {%0,%1,%2,%3};"
      : "+f"(d[0]), "+f"(d[1]), "+f"(d[2]), "+f"(d[3])
      : "r"(a0), "r"(a1), "r"(a2), "r"(a3), "r"(b0), "r"(b1));
}

// ---------------- scratch (device globals; no allocations) ----------------
__device__ unsigned g_bits[BB*NN*NWRD];
__device__ float g_Wh1[BB*NN*512];
__device__ float g_x1 [BB*NN*512];
__device__ float g_Wh2[BB*NN*128];
__device__ float g_att2[BB*NN*128];
__device__ float g_s1a[BB*NN*NH], g_s2a[BB*NN*NH];
__device__ float g_Aa [BB*NN*NH], g_Ca [BB*NN*NH];
__device__ float g_Pa [BB*NN*NH], g_Qa [BB*NN*NH];
__device__ float g_s1b[BB*NN], g_s2b[BB*NN];
__device__ float g_Ab [BB*NN], g_Cb [BB*NN];
__device__ float g_Pb [BB*NN], g_Qb [BB*NN];

// ---------------- adjacency bitmask ----------------
__global__ void k_bits(const int* __restrict__ adj) {
  int row = blockIdx.x;
  const int* a = adj + (size_t)row*NN;
  int lane = threadIdx.x & 31, w = threadIdx.x >> 5;
  for (int c = w; c < NWRD; c += 2) {
    unsigned m = __ballot_sync(0xffffffffu, a[c*32 + lane] > 0);
    if (lane == 0) g_bits[row*NWRD + c] = m;
  }
}

// ---------------- projection SGEMM (R6 config: 128x64 tile, 8i x 4f, f32x2) ----------------
template<int K, int MODE>
__global__ __launch_bounds__(256, 3) void k_proj(const float* __restrict__ Ain,
                                                 const float* __restrict__ Bsrc) {
  __shared__ float As[16][132];
  __shared__ float Bs[16][68];
  const float* A = (MODE==1) ? Ain : g_x1;
  float* C = (MODE==1) ? g_Wh1 : g_Wh2;
  const int ldc = (MODE==1) ? 512 : 128;
  int m0 = blockIdx.x*128, n0 = blockIdx.y*64;
  int tid = threadIdx.x;
  int tx = tid & 15, ty = tid >> 4;
  u64t acc2[4][4];
#pragma unroll
  for (int i=0;i<4;i++)
#pragma unroll
    for (int j=0;j<4;j++) acc2[i][j] = 0ull;
  for (int k0 = 0; k0 < K; k0 += 16) {
#pragma unroll
    for (int r = 0; r < 2; r++) {
      int m = (tid >> 2) + r*64, kq = (tid & 3) * 4;
      float4 v = *(const float4*)(A + (size_t)(m0+m)*K + k0 + kq);
      As[kq+0][m]=v.x; As[kq+1][m]=v.y; As[kq+2][m]=v.z; As[kq+3][m]=v.w;
    }
    {
      int k = tid >> 4, n4 = (tid & 15) * 4;
      float4 v;
      if (MODE==1) {
        int h = n0 >> 6;
        v = *(const float4*)(Bsrc + ((size_t)h*128 + k0 + k)*64 + n4);
      } else {
        v = *(const float4*)(Bsrc + (size_t)(k0+k)*128 + n0 + n4);
      }
      *(float4*)&Bs[k][n4] = v;
    }
    __syncthreads();
#pragma unroll 4
    for (int kk = 0; kk < 16; kk++) {
      ulonglong2 q0 = *(const ulonglong2*)&As[kk][ty*8];
      ulonglong2 q1 = *(const ulonglong2*)&As[kk][ty*8+4];
      float4 bv = *(const float4*)&Bs[kk][tx*4];
      u64t bb[4] = {bcast2(bv.x),bcast2(bv.y),bcast2(bv.z),bcast2(bv.w)};
      u64t aa[4] = {q0.x,q0.y,q1.x,q1.y};
#pragma unroll
      for (int ip=0;ip<4;ip++)
#pragma unroll
        for (int f=0;f<4;f++) acc2[ip][f] = ffma2(aa[ip], bb[f], acc2[ip][f]);
    }
    __syncthreads();
  }
#pragma unroll
  for (int ip=0;ip<4;ip++) {
    float2 u0 = unpk(acc2[ip][0]), u1 = unpk(acc2[ip][1]);
    float2 u2 = unpk(acc2[ip][2]), u3 = unpk(acc2[ip][3]);
    int ii0 = ty*8 + 2*ip;
    *(float4*)(C + (size_t)(m0 + ii0)*ldc + n0 + tx*4) =
        make_float4(u0.x,u1.x,u2.x,u3.x);
    *(float4*)(C + (size_t)(m0 + ii0+1)*ldc + n0 + tx*4) =
        make_float4(u0.y,u1.y,u2.y,u3.y);
  }
}

// ---------------- layer1 scores ----------------
__global__ __launch_bounds__(256) void k_scores1(const float* __restrict__ a_heads) {
  int row = blockIdx.x;
  int w = threadIdx.x >> 5, l = threadIdx.x & 31;
  const float* wh = g_Wh1 + (size_t)row*512 + w*64;
  const float* ah = a_heads + w*128;
  float s1 = wh[l]*ah[l]    + wh[l+32]*ah[l+32];
  float s2 = wh[l]*ah[64+l] + wh[l+32]*ah[96+l];
  for (int d=16; d; d>>=1) {
    s1 += __shfl_xor_sync(0xffffffffu, s1, d);
    s2 += __shfl_xor_sync(0xffffffffu, s2, d);
  }
  if (l == 0) {
    int idx = row*NH + w;
    g_s1a[idx] = s1; g_s2a[idx] = s2;
    g_Aa[idx] = __expf(s1); g_Ca[idx] = __expf(0.2f*s1);
    g_Pa[idx] = __expf(s2); g_Qa[idx] = __expf(0.2f*s2);
  }
}

// ---------------- layer2 scores ----------------
__global__ __launch_bounds__(256) void k_scores2(const float* __restrict__ a_out) {
  int row = blockIdx.x*8 + (threadIdx.x >> 5);
  int l = threadIdx.x & 31;
  const float* wh = g_Wh2 + (size_t)row*128;
  float s1=0.f, s2=0.f;
#pragma unroll
  for (int r=0;r<4;r++){
    int o=l+r*32; float x=wh[o];
    s1 = fmaf(x, a_out[o], s1);
    s2 = fmaf(x, a_out[128+o], s2);
  }
  for (int d=16; d; d>>=1) {
    s1 += __shfl_xor_sync(0xffffffffu, s1, d);
    s2 += __shfl_xor_sync(0xffffffffu, s2, d);
  }
  if (l==0) {
    g_s1b[row]=s1; g_s2b[row]=s2;
    g_Ab[row]=__expf(s1); g_Cb[row]=__expf(0.2f*s1);
    g_Pb[row]=__expf(s2); g_Qb[row]=__expf(0.2f*s2);
  }
}

// ---------------- mma.sync tf32 fused masked-softmax attention @ Wh ----------------
// CTA 256 thr = 8 warps; tile 128 i x 64 f; warp w owns rows [w*16, w*16+16).
// m16n8k8: thread computes its own A-fragment p values directly (no A smem);
// B = Wh^T staged tf32 in smem [32 j][72 f] (conflict-free frag loads).
// Row-sum of tf32(p) accumulates in registers; 4-lane shfl matches D layout.
template<int LAYER>
__global__ __launch_bounds__(256, 3) void k_att_mma(const float* __restrict__ masks) {
  __shared__ float WhS[32][72];
  __shared__ float s2j[32], Pj[32], Qj[32];
  int b = blockIdx.z, sec = blockIdx.y, it = blockIdx.x;
  int i0 = it*128;
  int tid = threadIdx.x, lane = tid & 31, w = tid >> 5;
  int gid = lane >> 2, qid = lane & 3;
  const float* Wh = (LAYER==1) ? g_Wh1 : g_Wh2;
  const int ldw = (LAYER==1) ? 512 : 128;
  const int coff = sec*64;
  int row_lo = i0 + w*16 + gid;
  int row_hi = row_lo + 8;
  float s1_lo, A_lo, C_lo, s1_hi, A_hi, C_hi;
  {
    int n_lo = b*NN + row_lo, n_hi = b*NN + row_hi;
    int si_lo = (LAYER==1) ? n_lo*NH + sec : n_lo;
    int si_hi = (LAYER==1) ? n_hi*NH + sec : n_hi;
    s1_lo = (LAYER==1) ? g_s1a[si_lo] : g_s1b[si_lo];
    A_lo  = (LAYER==1) ? g_Aa[si_lo]  : g_Ab[si_lo];
    C_lo  = (LAYER==1) ? g_Ca[si_lo]  : g_Cb[si_lo];
    s1_hi = (LAYER==1) ? g_s1a[si_hi] : g_s1b[si_hi];
    A_hi  = (LAYER==1) ? g_Aa[si_hi]  : g_Ab[si_hi];
    C_hi  = (LAYER==1) ? g_Ca[si_hi]  : g_Cb[si_hi];
  }
  const unsigned* brow_lo = g_bits + (size_t)(b*NN + row_lo)*NWRD;
  const unsigned* brow_hi = g_bits + (size_t)(b*NN + row_hi)*NWRD;
  float d[8][4];
#pragma unroll
  for (int nt=0;nt<8;nt++)
#pragma unroll
    for (int e=0;e<4;e++) d[nt][e] = 0.f;
  float rs_lo = 0.f, rs_hi = 0.f;

  for (int jt = 0; jt < 16; jt++) {
    __syncthreads();
    // stage B tile (32 j x 64 f) as tf32; 8 floats/thread
#pragma unroll
    for (int r = 0; r < 2; r++) {
      int task = tid + r*256;
      int j = task >> 4, f4 = (task & 15) * 4;
      float4 v = *(const float4*)(Wh + (size_t)(b*NN + jt*32 + j)*ldw + coff + f4);
      WhS[j][f4+0] = tf32r(v.x); WhS[j][f4+1] = tf32r(v.y);
      WhS[j][f4+2] = tf32r(v.z); WhS[j][f4+3] = tf32r(v.w);
    }
    if (tid < 32) {
      int node = b*NN + jt*32 + tid;
      int si = (LAYER==1) ? node*NH + sec : node;
      s2j[tid] = (LAYER==1) ? g_s2a[si] : g_s2b[si];
      Pj[tid]  = (LAYER==1) ? g_Pa[si]  : g_Pb[si];
      Qj[tid]  = (LAYER==1) ? g_Qa[si]  : g_Qb[si];
    }
    __syncthreads();
    unsigned wl = brow_lo[jt], wh_ = brow_hi[jt];
#pragma unroll
    for (int kk = 0; kk < 4; kk++) {
      int j0 = kk*8 + qid, j1 = j0 + 4;
      float t_s2_0 = s2j[j0], t_p0 = Pj[j0], t_q0 = Qj[j0];
      float t_s2_1 = s2j[j1], t_p1 = Pj[j1], t_q1 = Qj[j1];
      float p00 = 0.f, p10 = 0.f, p01 = 0.f, p11 = 0.f;
      if ((wl  >> j0) & 1u) { float sv = s1_lo + t_s2_0; p00 = tf32r((sv > 0.f) ? A_lo*t_p0 : C_lo*t_q0); }
      if ((wh_ >> j0) & 1u) { float sv = s1_hi + t_s2_0; p10 = tf32r((sv > 0.f) ? A_hi*t_p0 : C_hi*t_q0); }
      if ((wl  >> j1) & 1u) { float sv = s1_lo + t_s2_1; p01 = tf32r((sv > 0.f) ? A_lo*t_p1 : C_lo*t_q1); }
      if ((wh_ >> j1) & 1u) { float sv = s1_hi + t_s2_1; p11 = tf32r((sv > 0.f) ? A_hi*t_p1 : C_hi*t_q1); }
      rs_lo += p00 + p01;
      rs_hi += p10 + p11;
      uint32_t a0 = __float_as_uint(p00), a1 = __float_as_uint(p10);
      uint32_t a2 = __float_as_uint(p01), a3 = __float_as_uint(p11);
#pragma unroll
      for (int nt = 0; nt < 8; nt++) {
        uint32_t b0 = __float_as_uint(WhS[j0][nt*8 + gid]);
        uint32_t b1 = __float_as_uint(WhS[j1][nt*8 + gid]);
        mma_tf32(d[nt], a0, a1, a2, a3, b0, b1);
      }
    }
  }
  // finalize rowsums: sum across the 4 lanes of each group (qid axis)
  rs_lo += __shfl_xor_sync(0xffffffffu, rs_lo, 1);
  rs_lo += __shfl_xor_sync(0xffffffffu, rs_lo, 2);
  rs_hi += __shfl_xor_sync(0xffffffffu, rs_hi, 1);
  rs_hi += __shfl_xor_sync(0xffffffffu, rs_hi, 2);
  float mk_lo = masks[b*NN + row_lo], mk_hi = masks[b*NN + row_hi];
  float sc_lo = ((rs_lo > 0.f) ? 1.f/rs_lo : 0.f) * ((LAYER==1) ? mk_lo : mk_lo*mk_lo);
  float sc_hi = ((rs_hi > 0.f) ? 1.f/rs_hi : 0.f) * ((LAYER==1) ? mk_hi : mk_hi*mk_hi);
  float* outp = (LAYER==1) ? g_x1 : g_att2;
  const int ldo = (LAYER==1) ? 512 : 128;
  float* orow_lo = outp + (size_t)(b*NN + row_lo)*ldo + coff;
  float* orow_hi = outp + (size_t)(b*NN + row_hi)*ldo + coff;
#pragma unroll
  for (int nt = 0; nt < 8; nt++) {
    int fo = nt*8 + qid*2;
    float v0 = d[nt][0]*sc_lo, v1 = d[nt][1]*sc_lo;
    float v2 = d[nt][2]*sc_hi, v3 = d[nt][3]*sc_hi;
    if (LAYER==1) {
      v0 = (v0 > 0.f) ? v0 : expm1f(v0);
      v1 = (v1 > 0.f) ? v1 : expm1f(v1);
      v2 = (v2 > 0.f) ? v2 : expm1f(v2);
      v3 = (v3 > 0.f) ? v3 : expm1f(v3);
    }
    *(float2*)(orow_lo + fo) = make_float2(v0, v1);
    *(float2*)(orow_hi + fo) = make_float2(v2, v3);
  }
}

// ---------------- node select + 3-layer MLP + softmax ----------------
__global__ __launch_bounds__(256) void k_mlp(
    const int* __restrict__ node_order_i32,
    const float* __restrict__ work, const float* __restrict__ sub,
    const float* __restrict__ w1, const float* __restrict__ b1,
    const float* __restrict__ w2, const float* __restrict__ b2,
    const float* __restrict__ w3, const float* __restrict__ b3,
    float* __restrict__ out) {
  __shared__ float inf[192];
  __shared__ float h1[256];
  __shared__ float h2[256];
  __shared__ float red[8];
  __shared__ float sval;
  __shared__ int snd;
  int b = blockIdx.x, t = threadIdx.x;
  if (t == 0) {
    bool is64 = true;
    for (int i = 1; i < 32; i += 2) is64 = is64 && (node_order_i32[i] == 0);
    snd = is64 ? node_order_i32[2*b] : node_order_i32[b];
  }
  __syncthreads();
  int nd = snd;
  const float* sel = g_att2 + ((size_t)b*NN + nd)*128;
  if (t < 128)       inf[t] = sel[t];
  else if (t < 160)  inf[t] = work[b*32 + (t-128)];
  else if (t < 192)  inf[t] = sub[b*32 + (t-160)];
  __syncthreads();
  float s = b1[t];
  for (int k=0;k<192;k++) s = fmaf(inf[k], w1[k*256+t], s);
  h1[t] = fmaxf(s, 0.f);
  __syncthreads();
  s = b2[t];
  for (int k=0;k<256;k++) s = fmaf(h1[k], w2[k*256+t], s);
  h2[t] = fmaxf(s, 0.f);
  __syncthreads();
  float s0 = b3[t], s1 = b3[256+t];
  for (int k=0;k<256;k++) {
    float h = h2[k];
    s0 = fmaf(h, w3[k*512+t], s0);
    s1 = fmaf(h, w3[k*512+256+t], s1);
  }
  float mx = fmaxf(s0, s1);
  for (int d=16; d; d>>=1) mx = fmaxf(mx, __shfl_xor_sync(0xffffffffu, mx, d));
  if ((t&31)==0) red[t>>5] = mx;
  __syncthreads();
  if (t == 0) { float m = red[0]; for (int i=1;i<8;i++) m = fmaxf(m, red[i]); sval = m; }
  __syncthreads();
  float m = sval;
  float e0 = __expf(s0 - m), e1 = __expf(s1 - m);
  float ps = e0 + e1;
  for (int d=16; d; d>>=1) ps += __shfl_xor_sync(0xffffffffu, ps, d);
  if ((t&31)==0) red[t>>5] = ps;
  __syncthreads();
  if (t == 0) { float q = 0.f; for (int i=0;i<8;i++) q += red[i]; sval = q; }
  __syncthreads();
  float inv = 1.f / sval;
  out[b*512 + t]       = e0*inv;
  out[b*512 + 256 + t] = e1*inv;
}

// ---------------- launcher ----------------
extern "C" void kernel_launch(void* const* d_in, const int* in_sizes, int n_in,
                              void* d_out, int out_size) {
  const float* graph_inf  = (const float*)d_in[0];
  const int*   adj        = (const int*)d_in[1];
  const float* masks      = (const float*)d_in[2];
  const int*   node_order = (const int*)d_in[3];
  const float* work       = (const float*)d_in[4];
  const float* subtask    = (const float*)d_in[5];
  const float* W_heads    = (const float*)d_in[6];
  const float* a_heads    = (const float*)d_in[7];
  const float* W_out      = (const float*)d_in[8];
  const float* a_out      = (const float*)d_in[9];
  const float* fc1w       = (const float*)d_in[10];
  const float* fc1b       = (const float*)d_in[11];
  const float* fc2w       = (const float*)d_in[12];
  const float* fc2b       = (const float*)d_in[13];
  const float* fc3w       = (const float*)d_in[14];
  const float* fc3b       = (const float*)d_in[15];
  float* out = (float*)d_out;
  (void)in_sizes; (void)n_in; (void)out_size;

  k_bits<<<BB*NN, 64>>>(adj);
  k_proj<128,1><<<dim3(128, 8), 256>>>(graph_inf, W_heads);
  k_scores1<<<BB*NN, 256>>>(a_heads);
  k_att_mma<1><<<dim3(4, 8, BB), 256>>>(masks);
  k_proj<512,2><<<dim3(128, 2), 256>>>(nullptr, W_out);
  k_scores2<<<BB*NN/8, 256>>>(a_out);
  k_att_mma<2><<<dim3(4, 2, BB), 256>>>(masks);
  k_mlp<<<BB, 256>>>(node_order, work, subtask,
                     fc1w, fc1b, fc2w, fc2b, fc3w, fc3b, out);
}

// round 12
// speedup vs baseline: 1.8774x; 1.1821x over previous
#include <cuda_runtime.h>
#include <math.h>
#include <stdint.h>

#define BB 32
#define NN 512
#define NH 8
#define NWRD 16   // 512/32 bitmask words per adjacency row

// ---------------- ptx helpers ----------------
__device__ __forceinline__ float tf32r(float x) {
  float r; asm("cvt.rna.tf32.f32 %0, %1;" : "=f"(r) : "f"(x));
  return r;
}
// warp-level tf32 MMA (m16n8k8; runs on tensor pipe via base-target HMMA)
__device__ __forceinline__ void mma_tf32(float* d, uint32_t a0, uint32_t a1,
                                         uint32_t a2, uint32_t a3,
                                         uint32_t b0, uint32_t b1) {
  asm volatile(
      "mma.sync.aligned.m16n8k8.row.col.f32.tf32.tf32.f32 "
      "{%0,%1,%2,%3}, {%4,%5,%6,%7}, {%8,%9}, {%0,%1,%2,%3};"
      : "+f"(d[0]), "+f"(d[1]), "+f"(d[2]), "+f"(d[3])
      : "r"(a0), "r"(a1), "r"(a2), "r"(a3), "r"(b0), "r"(b1));
}

// ---------------- scratch (device globals; no allocations) ----------------
__device__ unsigned g_bits[BB*NN*NWRD];
__device__ float g_Wh1[BB*NN*512];
__device__ float g_x1 [BB*NN*512];
__device__ float g_Wh2[BB*NN*128];
__device__ float g_att2[BB*NN*128];
__device__ float g_s1a[BB*NN*NH], g_s2a[BB*NN*NH];
__device__ float g_Aa [BB*NN*NH], g_Ca [BB*NN*NH];
__device__ float g_Pa [BB*NN*NH], g_Qa [BB*NN*NH];
__device__ float g_s1b[BB*NN], g_s2b[BB*NN];
__device__ float g_Ab [BB*NN], g_Cb [BB*NN];
__device__ float g_Pb [BB*NN], g_Qb [BB*NN];

// ---------------- adjacency bitmask ----------------
__global__ void k_bits(const int* __restrict__ adj) {
  int row = blockIdx.x;
  const int* a = adj + (size_t)row*NN;
  int lane = threadIdx.x & 31, w = threadIdx.x >> 5;
  for (int c = w; c < NWRD; c += 2) {
    unsigned m = __ballot_sync(0xffffffffu, a[c*32 + lane] > 0);
    if (lane == 0) g_bits[row*NWRD + c] = m;
  }
}

// ---------------- mma.sync tf32 projection GEMM ----------------
// CTA 256 thr = 8 warps; tile 128 m x 64 n; warp w owns rows [w*16, w*16+16).
// K-chunks of 32.  As: [row][36] k-major (conflict-free frag + staging).
// Bs: [n][32] with k' = k ^ ((n&7)*4) swizzle (conflict-free frag loads).
// MODE 1: A=graph_inf (K=128), B=W_heads [h][k][n], C=g_Wh1 (ldc 512),
//         + fused layer1 scores epilogue (s1,s2,A,C,P,Q per node/head).
// MODE 2: A=g_x1 (K=512), B=W_out [512,128], C=g_Wh2 (ldc 128).
template<int K, int MODE>
__global__ __launch_bounds__(256) void k_proj_mma(const float* __restrict__ Ain,
                                                  const float* __restrict__ Bsrc,
                                                  const float* __restrict__ a_heads) {
  __shared__ float As[128*36];
  __shared__ float Bs[64*32];
  __shared__ float ahs[128];
  const float* A = (MODE==1) ? Ain : g_x1;
  float* C = (MODE==1) ? g_Wh1 : g_Wh2;
  const int ldc = (MODE==1) ? 512 : 128;
  int m0 = blockIdx.x*128, n0 = blockIdx.y*64;
  int sec = blockIdx.y;
  int tid = threadIdx.x, lane = tid & 31, w = tid >> 5;
  int gid = lane >> 2, qid = lane & 3;
  if (MODE==1 && tid < 128) ahs[tid] = a_heads[sec*128 + tid];
  float d[8][4];
#pragma unroll
  for (int nt=0;nt<8;nt++)
#pragma unroll
    for (int e=0;e<4;e++) d[nt][e] = 0.f;

  for (int k0 = 0; k0 < K; k0 += 32) {
    __syncthreads();
    // stage A chunk: warp w covers rows w*16..+15, k = lane (coalesced LDG, cf STS)
#pragma unroll
    for (int r = 0; r < 16; r++) {
      int row = w*16 + r;
      float v = A[(size_t)(m0+row)*K + k0 + lane];
      As[row*36 + lane] = tf32r(v);
    }
    // stage B chunk: warp w covers k-rows w*4..+3, n = lane / lane+32
#pragma unroll
    for (int r = 0; r < 4; r++) {
      int k = w*4 + r;
#pragma unroll
      for (int h2 = 0; h2 < 2; h2++) {
        int n = lane + h2*32;
        float v;
        if (MODE==1) v = Bsrc[((size_t)sec*128 + k0 + k)*64 + n];
        else         v = Bsrc[(size_t)(k0+k)*128 + n0 + n];
        Bs[n*32 + (k ^ ((n & 7) * 4))] = tf32r(v);
      }
    }
    __syncthreads();
#pragma unroll
    for (int kk = 0; kk < 4; kk++) {
      int rb = w*16;
      uint32_t a0 = __float_as_uint(As[(rb+gid)*36   + kk*8 + qid]);
      uint32_t a1 = __float_as_uint(As[(rb+gid+8)*36 + kk*8 + qid]);
      uint32_t a2 = __float_as_uint(As[(rb+gid)*36   + kk*8 + qid+4]);
      uint32_t a3 = __float_as_uint(As[(rb+gid+8)*36 + kk*8 + qid+4]);
#pragma unroll
      for (int nt = 0; nt < 8; nt++) {
        int n = nt*8 + gid;
        uint32_t b0 = __float_as_uint(Bs[n*32 + ((kk*8+qid)   ^ ((n & 7) * 4))]);
        uint32_t b1 = __float_as_uint(Bs[n*32 + ((kk*8+qid+4) ^ ((n & 7) * 4))]);
        mma_tf32(d[nt], a0, a1, a2, a3, b0, b1);
      }
    }
  }
  // epilogue: C stores
  int row_lo = m0 + w*16 + gid, row_hi = row_lo + 8;
  float* c_lo = C + (size_t)row_lo*ldc + n0;
  float* c_hi = C + (size_t)row_hi*ldc + n0;
#pragma unroll
  for (int nt = 0; nt < 8; nt++) {
    int fo = nt*8 + qid*2;
    *(float2*)(c_lo + fo) = make_float2(d[nt][0], d[nt][1]);
    *(float2*)(c_hi + fo) = make_float2(d[nt][2], d[nt][3]);
  }
  if (MODE==1) {
    // fused layer1 scores: n-tile == one head; fragments hold complete rows
    float s1l=0.f, s2l=0.f, s1h=0.f, s2h=0.f;
#pragma unroll
    for (int nt = 0; nt < 8; nt++) {
      int f = nt*8 + qid*2;
      s1l += d[nt][0]*ahs[f]    + d[nt][1]*ahs[f+1];
      s2l += d[nt][0]*ahs[64+f] + d[nt][1]*ahs[64+f+1];
      s1h += d[nt][2]*ahs[f]    + d[nt][3]*ahs[f+1];
      s2h += d[nt][2]*ahs[64+f] + d[nt][3]*ahs[64+f+1];
    }
    s1l += __shfl_xor_sync(0xffffffffu, s1l, 1); s1l += __shfl_xor_sync(0xffffffffu, s1l, 2);
    s2l += __shfl_xor_sync(0xffffffffu, s2l, 1); s2l += __shfl_xor_sync(0xffffffffu, s2l, 2);
    s1h += __shfl_xor_sync(0xffffffffu, s1h, 1); s1h += __shfl_xor_sync(0xffffffffu, s1h, 2);
    s2h += __shfl_xor_sync(0xffffffffu, s2h, 1); s2h += __shfl_xor_sync(0xffffffffu, s2h, 2);
    if (qid == 0) {
      int i_lo = row_lo*NH + sec, i_hi = row_hi*NH + sec;
      g_s1a[i_lo] = s1l; g_s2a[i_lo] = s2l;
      g_Aa[i_lo] = __expf(s1l); g_Ca[i_lo] = __expf(0.2f*s1l);
      g_Pa[i_lo] = __expf(s2l); g_Qa[i_lo] = __expf(0.2f*s2l);
      g_s1a[i_hi] = s1h; g_s2a[i_hi] = s2h;
      g_Aa[i_hi] = __expf(s1h); g_Ca[i_hi] = __expf(0.2f*s1h);
      g_Pa[i_hi] = __expf(s2h); g_Qa[i_hi] = __expf(0.2f*s2h);
    }
  }
}

// ---------------- layer2 scores ----------------
__global__ __launch_bounds__(256) void k_scores2(const float* __restrict__ a_out) {
  int row = blockIdx.x*8 + (threadIdx.x >> 5);
  int l = threadIdx.x & 31;
  const float* wh = g_Wh2 + (size_t)row*128;
  float s1=0.f, s2=0.f;
#pragma unroll
  for (int r=0;r<4;r++){
    int o=l+r*32; float x=wh[o];
    s1 = fmaf(x, a_out[o], s1);
    s2 = fmaf(x, a_out[128+o], s2);
  }
  for (int d=16; d; d>>=1) {
    s1 += __shfl_xor_sync(0xffffffffu, s1, d);
    s2 += __shfl_xor_sync(0xffffffffu, s2, d);
  }
  if (l==0) {
    g_s1b[row]=s1; g_s2b[row]=s2;
    g_Ab[row]=__expf(s1); g_Cb[row]=__expf(0.2f*s1);
    g_Pb[row]=__expf(s2); g_Qb[row]=__expf(0.2f*s2);
  }
}

// ---------------- mma.sync tf32 fused masked-softmax attention @ Wh ----------------
// (unchanged from R9 — proven correct/fast)
template<int LAYER>
__global__ __launch_bounds__(256, 3) void k_att_mma(const float* __restrict__ masks) {
  __shared__ float WhS[32][72];
  __shared__ float s2j[32], Pj[32], Qj[32];
  int b = blockIdx.z, sec = blockIdx.y, it = blockIdx.x;
  int i0 = it*128;
  int tid = threadIdx.x, lane = tid & 31, w = tid >> 5;
  int gid = lane >> 2, qid = lane & 3;
  const float* Wh = (LAYER==1) ? g_Wh1 : g_Wh2;
  const int ldw = (LAYER==1) ? 512 : 128;
  const int coff = sec*64;
  int row_lo = i0 + w*16 + gid;
  int row_hi = row_lo + 8;
  float s1_lo, A_lo, C_lo, s1_hi, A_hi, C_hi;
  {
    int n_lo = b*NN + row_lo, n_hi = b*NN + row_hi;
    int si_lo = (LAYER==1) ? n_lo*NH + sec : n_lo;
    int si_hi = (LAYER==1) ? n_hi*NH + sec : n_hi;
    s1_lo = (LAYER==1) ? g_s1a[si_lo] : g_s1b[si_lo];
    A_lo  = (LAYER==1) ? g_Aa[si_lo]  : g_Ab[si_lo];
    C_lo  = (LAYER==1) ? g_Ca[si_lo]  : g_Cb[si_lo];
    s1_hi = (LAYER==1) ? g_s1a[si_hi] : g_s1b[si_hi];
    A_hi  = (LAYER==1) ? g_Aa[si_hi]  : g_Ab[si_hi];
    C_hi  = (LAYER==1) ? g_Ca[si_hi]  : g_Cb[si_hi];
  }
  const unsigned* brow_lo = g_bits + (size_t)(b*NN + row_lo)*NWRD;
  const unsigned* brow_hi = g_bits + (size_t)(b*NN + row_hi)*NWRD;
  float d[8][4];
#pragma unroll
  for (int nt=0;nt<8;nt++)
#pragma unroll
    for (int e=0;e<4;e++) d[nt][e] = 0.f;
  float rs_lo = 0.f, rs_hi = 0.f;

  for (int jt = 0; jt < 16; jt++) {
    __syncthreads();
#pragma unroll
    for (int r = 0; r < 2; r++) {
      int task = tid + r*256;
      int j = task >> 4, f4 = (task & 15) * 4;
      float4 v = *(const float4*)(Wh + (size_t)(b*NN + jt*32 + j)*ldw + coff + f4);
      WhS[j][f4+0] = tf32r(v.x); WhS[j][f4+1] = tf32r(v.y);
      WhS[j][f4+2] = tf32r(v.z); WhS[j][f4+3] = tf32r(v.w);
    }
    if (tid < 32) {
      int node = b*NN + jt*32 + tid;
      int si = (LAYER==1) ? node*NH + sec : node;
      s2j[tid] = (LAYER==1) ? g_s2a[si] : g_s2b[si];
      Pj[tid]  = (LAYER==1) ? g_Pa[si]  : g_Pb[si];
      Qj[tid]  = (LAYER==1) ? g_Qa[si]  : g_Qb[si];
    }
    __syncthreads();
    unsigned wl = brow_lo[jt], wh_ = brow_hi[jt];
#pragma unroll
    for (int kk = 0; kk < 4; kk++) {
      int j0 = kk*8 + qid, j1 = j0 + 4;
      float t_s2_0 = s2j[j0], t_p0 = Pj[j0], t_q0 = Qj[j0];
      float t_s2_1 = s2j[j1], t_p1 = Pj[j1], t_q1 = Qj[j1];
      float p00 = 0.f, p10 = 0.f, p01 = 0.f, p11 = 0.f;
      if ((wl  >> j0) & 1u) { float sv = s1_lo + t_s2_0; p00 = tf32r((sv > 0.f) ? A_lo*t_p0 : C_lo*t_q0); }
      if ((wh_ >> j0) & 1u) { float sv = s1_hi + t_s2_0; p10 = tf32r((sv > 0.f) ? A_hi*t_p0 : C_hi*t_q0); }
      if ((wl  >> j1) & 1u) { float sv = s1_lo + t_s2_1; p01 = tf32r((sv > 0.f) ? A_lo*t_p1 : C_lo*t_q1); }
      if ((wh_ >> j1) & 1u) { float sv = s1_hi + t_s2_1; p11 = tf32r((sv > 0.f) ? A_hi*t_p1 : C_hi*t_q1); }
      rs_lo += p00 + p01;
      rs_hi += p10 + p11;
      uint32_t a0 = __float_as_uint(p00), a1 = __float_as_uint(p10);
      uint32_t a2 = __float_as_uint(p01), a3 = __float_as_uint(p11);
#pragma unroll
      for (int nt = 0; nt < 8; nt++) {
        uint32_t b0 = __float_as_uint(WhS[j0][nt*8 + gid]);
        uint32_t b1 = __float_as_uint(WhS[j1][nt*8 + gid]);
        mma_tf32(d[nt], a0, a1, a2, a3, b0, b1);
      }
    }
  }
  rs_lo += __shfl_xor_sync(0xffffffffu, rs_lo, 1);
  rs_lo += __shfl_xor_sync(0xffffffffu, rs_lo, 2);
  rs_hi += __shfl_xor_sync(0xffffffffu, rs_hi, 1);
  rs_hi += __shfl_xor_sync(0xffffffffu, rs_hi, 2);
  float mk_lo = masks[b*NN + row_lo], mk_hi = masks[b*NN + row_hi];
  float sc_lo = ((rs_lo > 0.f) ? 1.f/rs_lo : 0.f) * ((LAYER==1) ? mk_lo : mk_lo*mk_lo);
  float sc_hi = ((rs_hi > 0.f) ? 1.f/rs_hi : 0.f) * ((LAYER==1) ? mk_hi : mk_hi*mk_hi);
  float* outp = (LAYER==1) ? g_x1 : g_att2;
  const int ldo = (LAYER==1) ? 512 : 128;
  float* orow_lo = outp + (size_t)(b*NN + row_lo)*ldo + coff;
  float* orow_hi = outp + (size_t)(b*NN + row_hi)*ldo + coff;
#pragma unroll
  for (int nt = 0; nt < 8; nt++) {
    int fo = nt*8 + qid*2;
    float v0 = d[nt][0]*sc_lo, v1 = d[nt][1]*sc_lo;
    float v2 = d[nt][2]*sc_hi, v3 = d[nt][3]*sc_hi;
    if (LAYER==1) {
      v0 = (v0 > 0.f) ? v0 : expm1f(v0);
      v1 = (v1 > 0.f) ? v1 : expm1f(v1);
      v2 = (v2 > 0.f) ? v2 : expm1f(v2);
      v3 = (v3 > 0.f) ? v3 : expm1f(v3);
    }
    *(float2*)(orow_lo + fo) = make_float2(v0, v1);
    *(float2*)(orow_hi + fo) = make_float2(v2, v3);
  }
}

// ---------------- node select + 3-layer MLP + softmax ----------------
__global__ __launch_bounds__(256) void k_mlp(
    const int* __restrict__ node_order_i32,
    const float* __restrict__ work, const float* __restrict__ sub,
    const float* __restrict__ w1, const float* __restrict__ b1,
    const float* __restrict__ w2, const float* __restrict__ b2,
    const float* __restrict__ w3, const float* __restrict__ b3,
    float* __restrict__ out) {
  __shared__ float inf[192];
  __shared__ float h1[256];
  __shared__ float h2[256];
  __shared__ float red[8];
  __shared__ float sval;
  __shared__ int snd;
  int b = blockIdx.x, t = threadIdx.x;
  if (t == 0) {
    bool is64 = true;
    for (int i = 1; i < 32; i += 2) is64 = is64 && (node_order_i32[i] == 0);
    snd = is64 ? node_order_i32[2*b] : node_order_i32[b];
  }
  __syncthreads();
  int nd = snd;
  const float* sel = g_att2 + ((size_t)b*NN + nd)*128;
  if (t < 128)       inf[t] = sel[t];
  else if (t < 160)  inf[t] = work[b*32 + (t-128)];
  else if (t < 192)  inf[t] = sub[b*32 + (t-160)];
  __syncthreads();
  float s = b1[t];
  for (int k=0;k<192;k++) s = fmaf(inf[k], w1[k*256+t], s);
  h1[t] = fmaxf(s, 0.f);
  __syncthreads();
  s = b2[t];
  for (int k=0;k<256;k++) s = fmaf(h1[k], w2[k*256+t], s);
  h2[t] = fmaxf(s, 0.f);
  __syncthreads();
  float s0 = b3[t], s1 = b3[256+t];
  for (int k=0;k<256;k++) {
    float h = h2[k];
    s0 = fmaf(h, w3[k*512+t], s0);
    s1 = fmaf(h, w3[k*512+256+t], s1);
  }
  float mx = fmaxf(s0, s1);
  for (int d=16; d; d>>=1) mx = fmaxf(mx, __shfl_xor_sync(0xffffffffu, mx, d));
  if ((t&31)==0) red[t>>5] = mx;
  __syncthreads();
  if (t == 0) { float m = red[0]; for (int i=1;i<8;i++) m = fmaxf(m, red[i]); sval = m; }
  __syncthreads();
  float m = sval;
  float e0 = __expf(s0 - m), e1 = __expf(s1 - m);
  float ps = e0 + e1;
  for (int d=16; d; d>>=1) ps += __shfl_xor_sync(0xffffffffu, ps, d);
  if ((t&31)==0) red[t>>5] = ps;
  __syncthreads();
  if (t == 0) { float q = 0.f; for (int i=0;i<8;i++) q += red[i]; sval = q; }
  __syncthreads();
  float inv = 1.f / sval;
  out[b*512 + t]       = e0*inv;
  out[b*512 + 256 + t] = e1*inv;
}

// ---------------- launcher ----------------
extern "C" void kernel_launch(void* const* d_in, const int* in_sizes, int n_in,
                              void* d_out, int out_size) {
  const float* graph_inf  = (const float*)d_in[0];
  const int*   adj        = (const int*)d_in[1];
  const float* masks      = (const float*)d_in[2];
  const int*   node_order = (const int*)d_in[3];
  const float* work       = (const float*)d_in[4];
  const float* subtask    = (const float*)d_in[5];
  const float* W_heads    = (const float*)d_in[6];
  const float* a_heads    = (const float*)d_in[7];
  const float* W_out      = (const float*)d_in[8];
  const float* a_out      = (const float*)d_in[9];
  const float* fc1w       = (const float*)d_in[10];
  const float* fc1b       = (const float*)d_in[11];
  const float* fc2w       = (const float*)d_in[12];
  const float* fc2b       = (const float*)d_in[13];
  const float* fc3w       = (const float*)d_in[14];
  const float* fc3b       = (const float*)d_in[15];
  float* out = (float*)d_out;
  (void)in_sizes; (void)n_in; (void)out_size;

  k_bits<<<BB*NN, 64>>>(adj);
  k_proj_mma<128,1><<<dim3(128, 8), 256>>>(graph_inf, W_heads, a_heads);
  k_att_mma<1><<<dim3(4, 8, BB), 256>>>(masks);
  k_proj_mma<512,2><<<dim3(128, 2), 256>>>(nullptr, W_out, nullptr);
  k_scores2<<<BB*NN/8, 256>>>(a_out);
  k_att_mma<2><<<dim3(4, 2, BB), 256>>>(masks);
  k_mlp<<<BB, 256>>>(node_order, work, subtask,
                     fc1w, fc1b, fc2w, fc2b, fc3w, fc3b, out);
}

// round 17
// speedup vs baseline: 2.0321x; 1.0824x over previous
#include <cuda_runtime.h>
#include <math.h>
#include <stdint.h>

#define BB 32
#define NN 512
#define NH 8
#define NWRD 16   // 512/32 bitmask words per adjacency row

// ---------------- ptx helpers ----------------
__device__ __forceinline__ float tf32r(float x) {
  float r; asm("cvt.rna.tf32.f32 %0, %1;" : "=f"(r) : "f"(x));
  return r;
}
// warp-level tf32 MMA (m16n8k8; tensor pipe via base-target HMMA)
__device__ __forceinline__ void mma_tf32(float* d, uint32_t a0, uint32_t a1,
                                         uint32_t a2, uint32_t a3,
                                         uint32_t b0, uint32_t b1) {
  asm volatile(
      "mma.sync.aligned.m16n8k8.row.col.f32.tf32.tf32.f32 "
      "{%0,%1,%2,%3}, {%4,%5,%6,%7}, {%8,%9}, {%0,%1,%2,%3};"
      : "+f"(d[0]), "+f"(d[1]), "+f"(d[2]), "+f"(d[3])
      : "r"(a0), "r"(a1), "r"(a2), "r"(a3), "r"(b0), "r"(b1));
}

// ---------------- scratch (device globals; no allocations) ----------------
__device__ unsigned g_bits[BB*NN*NWRD];
__device__ float g_Wh1[BB*NN*512];
__device__ float g_x1 [BB*NN*512];
__device__ float g_Wh2[BB*NN*128];
__device__ float g_att2[BB*NN*128];
__device__ float g_s1a[BB*NN*NH], g_s2a[BB*NN*NH];
__device__ float g_Aa [BB*NN*NH], g_Ca [BB*NN*NH];
__device__ float g_Pa [BB*NN*NH], g_Qa [BB*NN*NH];
__device__ float g_s1b[BB*NN], g_s2b[BB*NN];
__device__ float g_Ab [BB*NN], g_Cb [BB*NN];
__device__ float g_Pb [BB*NN], g_Qb [BB*NN];

// ---------------- adjacency bitmask ----------------
__global__ void k_bits(const int* __restrict__ adj) {
  int row = blockIdx.x;
  const int* a = adj + (size_t)row*NN;
  int lane = threadIdx.x & 31, w = threadIdx.x >> 5;
  for (int c = w; c < NWRD; c += 2) {
    unsigned m = __ballot_sync(0xffffffffu, a[c*32 + lane] > 0);
    if (lane == 0) g_bits[row*NWRD + c] = m;
  }
}

// ---------------- mma.sync tf32 projection GEMM (register-prefetch pipelined) ----------------
// CTA 256 thr = 8 warps; tile 128 m x 64 n; warp w owns rows [w*16, w*16+16).
// K-chunks of 32.  As: [row][36] k-major; Bs: [n][32], k' = k ^ ((n&7)*4).
// MODE 1: A=graph_inf (K=128), B=W_heads [h][k][n], C=g_Wh1 (ldc 512),
//         + fused layer1 scores epilogue.
// MODE 2: A=g_x1 (K=512), B=W_out [512,128], C=g_Wh2 (ldc 128).
template<int K, int MODE>
__global__ __launch_bounds__(256) void k_proj_mma(const float* __restrict__ Ain,
                                                  const float* __restrict__ Bsrc,
                                                  const float* __restrict__ a_heads) {
  __shared__ float As[128*36];
  __shared__ float Bs[64*32];
  __shared__ float ahs[128];
  const float* A = (MODE==1) ? Ain : g_x1;
  float* C = (MODE==1) ? g_Wh1 : g_Wh2;
  const int ldc = (MODE==1) ? 512 : 128;
  constexpr int NC = K/32;
  int m0 = blockIdx.x*128, n0 = blockIdx.y*64;
  int sec = blockIdx.y;
  int tid = threadIdx.x, lane = tid & 31, w = tid >> 5;
  int gid = lane >> 2, qid = lane & 3;
  if (MODE==1 && tid < 128) ahs[tid] = a_heads[sec*128 + tid];
  float d[8][4];
#pragma unroll
  for (int nt=0;nt<8;nt++)
#pragma unroll
    for (int e=0;e<4;e++) d[nt][e] = 0.f;

  int arow = w*16 + (lane >> 1);
  int aq = (lane & 1) * 16;
  float4 ar[4];
  float br[8];

#define PROJ_LOAD(cc) do {                                                    \
    int k0_ = (cc)*32;                                                        \
    _Pragma("unroll")                                                         \
    for (int r = 0; r < 4; r++)                                               \
      ar[r] = *(const float4*)(A + (size_t)(m0+arow)*K + k0_ + aq + r*4);     \
    _Pragma("unroll")                                                         \
    for (int r = 0; r < 4; r++) {                                             \
      int k_ = w*4 + r;                                                       \
      _Pragma("unroll")                                                       \
      for (int h2 = 0; h2 < 2; h2++) {                                        \
        int n_ = lane + h2*32;                                                \
        br[r*2+h2] = (MODE==1)                                                \
            ? Bsrc[((size_t)sec*128 + k0_ + k_)*64 + n_]                      \
            : Bsrc[(size_t)(k0_+k_)*128 + n0 + n_];                           \
      }                                                                       \
    }                                                                         \
  } while(0)

  PROJ_LOAD(0);
  for (int c = 0; c < NC; c++) {
    __syncthreads();
#pragma unroll
    for (int r = 0; r < 4; r++) {
      float4 v = ar[r];
      v.x=tf32r(v.x); v.y=tf32r(v.y); v.z=tf32r(v.z); v.w=tf32r(v.w);
      *(float4*)&As[arow*36 + aq + r*4] = v;
    }
#pragma unroll
    for (int r = 0; r < 4; r++) {
      int k = w*4 + r;
#pragma unroll
      for (int h2 = 0; h2 < 2; h2++) {
        int n = lane + h2*32;
        Bs[n*32 + (k ^ ((n & 7) * 4))] = tf32r(br[r*2+h2]);
      }
    }
    __syncthreads();
    if (c+1 < NC) PROJ_LOAD(c+1);   // LDG in flight under the MMAs below
#pragma unroll
    for (int kk = 0; kk < 4; kk++) {
      int rb = w*16;
      uint32_t a0 = __float_as_uint(As[(rb+gid)*36   + kk*8 + qid]);
      uint32_t a1 = __float_as_uint(As[(rb+gid+8)*36 + kk*8 + qid]);
      uint32_t a2 = __float_as_uint(As[(rb+gid)*36   + kk*8 + qid+4]);
      uint32_t a3 = __float_as_uint(As[(rb+gid+8)*36 + kk*8 + qid+4]);
#pragma unroll
      for (int nt = 0; nt < 8; nt++) {
        int n = nt*8 + gid;
        uint32_t b0 = __float_as_uint(Bs[n*32 + ((kk*8+qid)   ^ ((n & 7) * 4))]);
        uint32_t b1 = __float_as_uint(Bs[n*32 + ((kk*8+qid+4) ^ ((n & 7) * 4))]);
        mma_tf32(d[nt], a0, a1, a2, a3, b0, b1);
      }
    }
  }
#undef PROJ_LOAD
  // epilogue: C stores
  int row_lo = m0 + w*16 + gid, row_hi = row_lo + 8;
  float* c_lo = C + (size_t)row_lo*ldc + n0;
  float* c_hi = C + (size_t)row_hi*ldc + n0;
#pragma unroll
  for (int nt = 0; nt < 8; nt++) {
    int fo = nt*8 + qid*2;
    *(float2*)(c_lo + fo) = make_float2(d[nt][0], d[nt][1]);
    *(float2*)(c_hi + fo) = make_float2(d[nt][2], d[nt][3]);
  }
  if (MODE==1) {
    float s1l=0.f, s2l=0.f, s1h=0.f, s2h=0.f;
#pragma unroll
    for (int nt = 0; nt < 8; nt++) {
      int f = nt*8 + qid*2;
      s1l += d[nt][0]*ahs[f]    + d[nt][1]*ahs[f+1];
      s2l += d[nt][0]*ahs[64+f] + d[nt][1]*ahs[64+f+1];
      s1h += d[nt][2]*ahs[f]    + d[nt][3]*ahs[f+1];
      s2h += d[nt][2]*ahs[64+f] + d[nt][3]*ahs[64+f+1];
    }
    s1l += __shfl_xor_sync(0xffffffffu, s1l, 1); s1l += __shfl_xor_sync(0xffffffffu, s1l, 2);
    s2l += __shfl_xor_sync(0xffffffffu, s2l, 1); s2l += __shfl_xor_sync(0xffffffffu, s2l, 2);
    s1h += __shfl_xor_sync(0xffffffffu, s1h, 1); s1h += __shfl_xor_sync(0xffffffffu, s1h, 2);
    s2h += __shfl_xor_sync(0xffffffffu, s2h, 1); s2h += __shfl_xor_sync(0xffffffffu, s2h, 2);
    if (qid == 0) {
      int i_lo = row_lo*NH + sec, i_hi = row_hi*NH + sec;
      g_s1a[i_lo] = s1l; g_s2a[i_lo] = s2l;
      g_Aa[i_lo] = __expf(s1l); g_Ca[i_lo] = __expf(0.2f*s1l);
      g_Pa[i_lo] = __expf(s2l); g_Qa[i_lo] = __expf(0.2f*s2l);
      g_s1a[i_hi] = s1h; g_s2a[i_hi] = s2h;
      g_Aa[i_hi] = __expf(s1h); g_Ca[i_hi] = __expf(0.2f*s1h);
      g_Pa[i_hi] = __expf(s2h); g_Qa[i_hi] = __expf(0.2f*s2h);
    }
  }
}

// ---------------- layer2 scores ----------------
__global__ __launch_bounds__(256) void k_scores2(const float* __restrict__ a_out) {
  int row = blockIdx.x*8 + (threadIdx.x >> 5);
  int l = threadIdx.x & 31;
  const float* wh = g_Wh2 + (size_t)row*128;
  float s1=0.f, s2=0.f;
#pragma unroll
  for (int r=0;r<4;r++){
    int o=l+r*32; float x=wh[o];
    s1 = fmaf(x, a_out[o], s1);
    s2 = fmaf(x, a_out[128+o], s2);
  }
  for (int d=16; d; d>>=1) {
    s1 += __shfl_xor_sync(0xffffffffu, s1, d);
    s2 += __shfl_xor_sync(0xffffffffu, s2, d);
  }
  if (l==0) {
    g_s1b[row]=s1; g_s2b[row]=s2;
    g_Ab[row]=__expf(s1); g_Cb[row]=__expf(0.2f*s1);
    g_Pb[row]=__expf(s2); g_Qb[row]=__expf(0.2f*s2);
  }
}

// ---------------- mma.sync tf32 fused masked-softmax attention (prefetch pipelined) ----------------
// CTA 256 thr = 8 warps; tile 128 i x 64 f; warp w owns rows [w*16, w*16+16).
// (s2,P,Q) packed as float4 -> 2 broadcast LDS.128 per kk in p-gen.
template<int LAYER>
__global__ __launch_bounds__(256) void k_att_mma(const float* __restrict__ masks) {
  __shared__ float WhS[32][72];
  __shared__ float4 sPQ[32];
  int b = blockIdx.z, sec = blockIdx.y, it = blockIdx.x;
  int i0 = it*128;
  int tid = threadIdx.x, lane = tid & 31, w = tid >> 5;
  int gid = lane >> 2, qid = lane & 3;
  const float* Wh = (LAYER==1) ? g_Wh1 : g_Wh2;
  const int ldw = (LAYER==1) ? 512 : 128;
  const int coff = sec*64;
  int row_lo = i0 + w*16 + gid;
  int row_hi = row_lo + 8;
  float s1_lo, A_lo, C_lo, s1_hi, A_hi, C_hi;
  {
    int n_lo = b*NN + row_lo, n_hi = b*NN + row_hi;
    int si_lo = (LAYER==1) ? n_lo*NH + sec : n_lo;
    int si_hi = (LAYER==1) ? n_hi*NH + sec : n_hi;
    s1_lo = (LAYER==1) ? g_s1a[si_lo] : g_s1b[si_lo];
    A_lo  = (LAYER==1) ? g_Aa[si_lo]  : g_Ab[si_lo];
    C_lo  = (LAYER==1) ? g_Ca[si_lo]  : g_Cb[si_lo];
    s1_hi = (LAYER==1) ? g_s1a[si_hi] : g_s1b[si_hi];
    A_hi  = (LAYER==1) ? g_Aa[si_hi]  : g_Ab[si_hi];
    C_hi  = (LAYER==1) ? g_Ca[si_hi]  : g_Cb[si_hi];
  }
  const unsigned* brow_lo = g_bits + (size_t)(b*NN + row_lo)*NWRD;
  const unsigned* brow_hi = g_bits + (size_t)(b*NN + row_hi)*NWRD;
  float d[8][4];
#pragma unroll
  for (int nt=0;nt<8;nt++)
#pragma unroll
    for (int e=0;e<4;e++) d[nt][e] = 0.f;
  float rs_lo = 0.f, rs_hi = 0.f;

  float4 wv[2];
  float p_s2 = 0.f, p_P = 0.f, p_Q = 0.f;
  unsigned pre_wl, pre_wh;

#define ATT_LOAD(jj) do {                                                        \
    _Pragma("unroll")                                                            \
    for (int r = 0; r < 2; r++) {                                                \
      int task = tid + r*256;                                                    \
      int j_ = task >> 4, f4_ = (task & 15) * 4;                                 \
      wv[r] = *(const float4*)(Wh + (size_t)(b*NN + (jj)*32 + j_)*ldw + coff + f4_); \
    }                                                                            \
    if (tid < 32) {                                                              \
      int node_ = b*NN + (jj)*32 + tid;                                          \
      int si_ = (LAYER==1) ? node_*NH + sec : node_;                             \
      p_s2 = (LAYER==1) ? g_s2a[si_] : g_s2b[si_];                               \
      p_P  = (LAYER==1) ? g_Pa[si_]  : g_Pb[si_];                                \
      p_Q  = (LAYER==1) ? g_Qa[si_]  : g_Qb[si_];                                \
    }                                                                            \
    pre_wl = brow_lo[jj]; pre_wh = brow_hi[jj];                                  \
  } while(0)

  ATT_LOAD(0);
  for (int jt = 0; jt < 16; jt++) {
    __syncthreads();
#pragma unroll
    for (int r = 0; r < 2; r++) {
      int task = tid + r*256;
      int j = task >> 4, f4 = (task & 15) * 4;
      float4 v = wv[r];
      WhS[j][f4+0] = tf32r(v.x); WhS[j][f4+1] = tf32r(v.y);
      WhS[j][f4+2] = tf32r(v.z); WhS[j][f4+3] = tf32r(v.w);
    }
    if (tid < 32) sPQ[tid] = make_float4(p_s2, p_P, p_Q, 0.f);
    unsigned wl = pre_wl, wh_ = pre_wh;
    __syncthreads();
    if (jt+1 < 16) ATT_LOAD(jt+1);   // LDG in flight under p-gen + MMA
#pragma unroll
    for (int kk = 0; kk < 4; kk++) {
      int j0 = kk*8 + qid, j1 = j0 + 4;
      float4 f0 = sPQ[j0], f1 = sPQ[j1];
      float p00 = 0.f, p10 = 0.f, p01 = 0.f, p11 = 0.f;
      if ((wl  >> j0) & 1u) { float sv = s1_lo + f0.x; p00 = tf32r((sv > 0.f) ? A_lo*f0.y : C_lo*f0.z); }
      if ((wh_ >> j0) & 1u) { float sv = s1_hi + f0.x; p10 = tf32r((sv > 0.f) ? A_hi*f0.y : C_hi*f0.z); }
      if ((wl  >> j1) & 1u) { float sv = s1_lo + f1.x; p01 = tf32r((sv > 0.f) ? A_lo*f1.y : C_lo*f1.z); }
      if ((wh_ >> j1) & 1u) { float sv = s1_hi + f1.x; p11 = tf32r((sv > 0.f) ? A_hi*f1.y : C_hi*f1.z); }
      rs_lo += p00 + p01;
      rs_hi += p10 + p11;
      uint32_t a0 = __float_as_uint(p00), a1 = __float_as_uint(p10);
      uint32_t a2 = __float_as_uint(p01), a3 = __float_as_uint(p11);
#pragma unroll
      for (int nt = 0; nt < 8; nt++) {
        uint32_t b0 = __float_as_uint(WhS[j0][nt*8 + gid]);
        uint32_t b1 = __float_as_uint(WhS[j1][nt*8 + gid]);
        mma_tf32(d[nt], a0, a1, a2, a3, b0, b1);
      }
    }
  }
#undef ATT_LOAD
  rs_lo += __shfl_xor_sync(0xffffffffu, rs_lo, 1);
  rs_lo += __shfl_xor_sync(0xffffffffu, rs_lo, 2);
  rs_hi += __shfl_xor_sync(0xffffffffu, rs_hi, 1);
  rs_hi += __shfl_xor_sync(0xffffffffu, rs_hi, 2);
  float mk_lo = masks[b*NN + row_lo], mk_hi = masks[b*NN + row_hi];
  float sc_lo = ((rs_lo > 0.f) ? 1.f/rs_lo : 0.f) * ((LAYER==1) ? mk_lo : mk_lo*mk_lo);
  float sc_hi = ((rs_hi > 0.f) ? 1.f/rs_hi : 0.f) * ((LAYER==1) ? mk_hi : mk_hi*mk_hi);
  float* outp = (LAYER==1) ? g_x1 : g_att2;
  const int ldo = (LAYER==1) ? 512 : 128;
  float* orow_lo = outp + (size_t)(b*NN + row_lo)*ldo + coff;
  float* orow_hi = outp + (size_t)(b*NN + row_hi)*ldo + coff;
#pragma unroll
  for (int nt = 0; nt < 8; nt++) {
    int fo = nt*8 + qid*2;
    float v0 = d[nt][0]*sc_lo, v1 = d[nt][1]*sc_lo;
    float v2 = d[nt][2]*sc_hi, v3 = d[nt][3]*sc_hi;
    if (LAYER==1) {
      v0 = (v0 > 0.f) ? v0 : expm1f(v0);
      v1 = (v1 > 0.f) ? v1 : expm1f(v1);
      v2 = (v2 > 0.f) ? v2 : expm1f(v2);
      v3 = (v3 > 0.f) ? v3 : expm1f(v3);
    }
    *(float2*)(orow_lo + fo) = make_float2(v0, v1);
    *(float2*)(orow_hi + fo) = make_float2(v2, v3);
  }
}

// ---------------- node select + 3-layer MLP + softmax ----------------
__global__ __launch_bounds__(256) void k_mlp(
    const int* __restrict__ node_order_i32,
    const float* __restrict__ work, const float* __restrict__ sub,
    const float* __restrict__ w1, const float* __restrict__ b1,
    const float* __restrict__ w2, const float* __restrict__ b2,
    const float* __restrict__ w3, const float* __restrict__ b3,
    float* __restrict__ out) {
  __shared__ float inf[192];
  __shared__ float h1[256];
  __shared__ float h2[256];
  __shared__ float red[8];
  __shared__ float sval;
  __shared__ int snd;
  int b = blockIdx.x, t = threadIdx.x;
  if (t == 0) {
    bool is64 = true;
    for (int i = 1; i < 32; i += 2) is64 = is64 && (node_order_i32[i] == 0);
    snd = is64 ? node_order_i32[2*b] : node_order_i32[b];
  }
  __syncthreads();
  int nd = snd;
  const float* sel = g_att2 + ((size_t)b*NN + nd)*128;
  if (t < 128)       inf[t] = sel[t];
  else if (t < 160)  inf[t] = work[b*32 + (t-128)];
  else if (t < 192)  inf[t] = sub[b*32 + (t-160)];
  __syncthreads();
  float s = b1[t];
  for (int k=0;k<192;k++) s = fmaf(inf[k], w1[k*256+t], s);
  h1[t] = fmaxf(s, 0.f);
  __syncthreads();
  s = b2[t];
  for (int k=0;k<256;k++) s = fmaf(h1[k], w2[k*256+t], s);
  h2[t] = fmaxf(s, 0.f);
  __syncthreads();
  float s0 = b3[t], s1 = b3[256+t];
  for (int k=0;k<256;k++) {
    float h = h2[k];
    s0 = fmaf(h, w3[k*512+t], s0);
    s1 = fmaf(h, w3[k*512+256+t], s1);
  }
  float mx = fmaxf(s0, s1);
  for (int d=16; d; d>>=1) mx = fmaxf(mx, __shfl_xor_sync(0xffffffffu, mx, d));
  if ((t&31)==0) red[t>>5] = mx;
  __syncthreads();
  if (t == 0) { float m = red[0]; for (int i=1;i<8;i++) m = fmaxf(m, red[i]); sval = m; }
  __syncthreads();
  float m = sval;
  float e0 = __expf(s0 - m), e1 = __expf(s1 - m);
  float ps = e0 + e1;
  for (int d=16; d; d>>=1) ps += __shfl_xor_sync(0xffffffffu, ps, d);
  if ((t&31)==0) red[t>>5] = ps;
  __syncthreads();
  if (t == 0) { float q = 0.f; for (int i=0;i<8;i++) q += red[i]; sval = q; }
  __syncthreads();
  float inv = 1.f / sval;
  out[b*512 + t]       = e0*inv;
  out[b*512 + 256 + t] = e1*inv;
}

// ---------------- launcher ----------------
extern "C" void kernel_launch(void* const* d_in, const int* in_sizes, int n_in,
                              void* d_out, int out_size) {
  const float* graph_inf  = (const float*)d_in[0];
  const int*   adj        = (const int*)d_in[1];
  const float* masks      = (const float*)d_in[2];
  const int*   node_order = (const int*)d_in[3];
  const float* work       = (const float*)d_in[4];
  const float* subtask    = (const float*)d_in[5];
  const float* W_heads    = (const float*)d_in[6];
  const float* a_heads    = (const float*)d_in[7];
  const float* W_out      = (const float*)d_in[8];
  const float* a_out      = (const float*)d_in[9];
  const float* fc1w       = (const float*)d_in[10];
  const float* fc1b       = (const float*)d_in[11];
  const float* fc2w       = (const float*)d_in[12];
  const float* fc2b       = (const float*)d_in[13];
  const float* fc3w       = (const float*)d_in[14];
  const float* fc3b       = (const float*)d_in[15];
  float* out = (float*)d_out;
  (void)in_sizes; (void)n_in; (void)out_size;

  k_bits<<<BB*NN, 64>>>(adj);
  k_proj_mma<128,1><<<dim3(128, 8), 256>>>(graph_inf, W_heads, a_heads);
  k_att_mma<1><<<dim3(4, 8, BB), 256>>>(masks);
  k_proj_mma<512,2><<<dim3(128, 2), 256>>>(nullptr, W_out, nullptr);
  k_scores2<<<BB*NN/8, 256>>>(a_out);
  k_att_mma<2><<<dim3(4, 2, BB), 256>>>(masks);
  k_mlp<<<BB, 256>>>(node_order, work, subtask,
                     fc1w, fc1b, fc2w, fc2b, fc3w, fc3b, out);
}